// round 16
// baseline (speedup 1.0000x reference)
#include <cuda_runtime.h>
#include <cuda_bf16.h>
#include <math.h>

#define T_SEQ   2048
#define BATCH   2
#define DM      1024
#define NH      16
#define DH      64
#define MROWS   (BATCH*T_SEQ)    /* 4096 */
#define N_QKV   (3*DM)           /* 3072 */

// Scratch (allocation-free rule: __device__ globals). 64 MB total.
__device__ float g_Q[MROWS*DM];
__device__ float g_K[MROWS*DM];
__device__ float g_V[MROWS*DM];
__device__ float g_attn[MROWS*DM];

// ---------------------------------------------------------------------------
// bf16 split helpers: x = hi + lo with |x - hi - lo| ~ 2^-18 |x|.
// pack two (even, odd) bf16 into one 32-bit fragment word (low = even).
// ---------------------------------------------------------------------------
__device__ __forceinline__ void split2(float a, float b, unsigned &hi, unsigned &lo)
{
    __nv_bfloat16 ha = __float2bfloat16_rn(a);
    __nv_bfloat16 hb = __float2bfloat16_rn(b);
    __nv_bfloat162 h; h.x = ha; h.y = hb;
    hi = *reinterpret_cast<unsigned*>(&h);
    __nv_bfloat162 l = __floats2bfloat162_rn(a - __bfloat162float(ha),
                                             b - __bfloat162float(hb));
    lo = *reinterpret_cast<unsigned*>(&l);
}

__device__ __forceinline__ void mma16816(float* d,
    unsigned a0, unsigned a1, unsigned a2, unsigned a3,
    unsigned b0, unsigned b1)
{
    asm volatile(
        "mma.sync.aligned.m16n8k16.row.col.f32.bf16.bf16.f32 "
        "{%0,%1,%2,%3}, {%4,%5,%6,%7}, {%8,%9}, {%0,%1,%2,%3};\n"
        : "+f"(d[0]), "+f"(d[1]), "+f"(d[2]), "+f"(d[3])
        : "r"(a0), "r"(a1), "r"(a2), "r"(a3), "r"(b0), "r"(b1));
}

// ---------------------------------------------------------------------------
// Tensor-core GEMM (R6 sync structure; NEW hi/lo-interleaved smem layout:
// word = row*40 + 2*pair + {0=hi,1=lo}, stride 20 pairs).
// Fragment loads become LDS.64 (conflict-free: (4g+t+8ks) mod 16 distinct),
// staging stores become STS.128. Smem bytes unchanged -> 2 CTAs/SM.
// Block 128x128x32, 8 warps (2x4), warp tile 64x32. 3-MMA bf16 split.
// ---------------------------------------------------------------------------
template<int NCOLS, bool SCATTER>
__global__ __launch_bounds__(256, 2)
void mma_gemm_kernel(const float* __restrict__ Ain, const float* __restrict__ W,
                     const float* __restrict__ bias, float* __restrict__ out)
{
    __shared__ unsigned sA[128*40], sB[128*40];   // 40960 B total

    const float* __restrict__ A = SCATTER ? Ain : (const float*)g_attn;

    const int tid  = threadIdx.x;
    const int lane = tid & 31;
    const int warp = tid >> 5;
    const int wm   = warp >> 2;     // 0..1
    const int wn   = warp & 3;      // 0..3
    const int g    = lane >> 2;     // 0..7
    const int t    = lane & 3;      // 0..3
    const int m0   = blockIdx.y * 128;
    const int n0   = blockIdx.x * 128;

    float acc[4][4][4];
#pragma unroll
    for (int mt = 0; mt < 4; mt++)
#pragma unroll
        for (int nt = 0; nt < 4; nt++)
#pragma unroll
            for (int i = 0; i < 4; i++) acc[mt][nt][i] = 0.f;

    const int ar  = tid >> 3;          // A row 0..31 (step 32)
    const int ak  = (tid & 7) << 2;    // A k offset
    const int bn  = tid & 127;         // B column (n)
    const int bk0 = (tid >> 7) << 2;   // 0 or 4

    for (int k0 = 0; k0 < DM; k0 += 32) {
        // ---- all LDGs before the barrier (proven ordering) ----
        float4 av[4];
#pragma unroll
        for (int i = 0; i < 4; i++)
            av[i] = *(const float4*)&A[(size_t)(m0 + ar + i * 32) * DM + k0 + ak];
        float bx[4][4];
#pragma unroll
        for (int gi = 0; gi < 4; gi++) {
            const int k = bk0 + gi * 8;
            const float* p = &W[(size_t)(k0 + k) * NCOLS + n0 + bn];
            bx[gi][0] = p[0];
            bx[gi][1] = p[NCOLS];
            bx[gi][2] = p[2 * NCOLS];
            bx[gi][3] = p[3 * NCOLS];
        }
        __syncthreads();               // previous tile fully consumed
#pragma unroll
        for (int i = 0; i < 4; i++) {
            const int r = ar + i * 32;
            unsigned h0, l0, h1, l1;
            split2(av[i].x, av[i].y, h0, l0);
            split2(av[i].z, av[i].w, h1, l1);
            *(uint4*)&sA[r * 40 + ak] = make_uint4(h0, l0, h1, l1);
        }
#pragma unroll
        for (int gi = 0; gi < 4; gi++) {
            const int k = bk0 + gi * 8;
            unsigned h0, l0, h1, l1;
            split2(bx[gi][0], bx[gi][1], h0, l0);
            split2(bx[gi][2], bx[gi][3], h1, l1);
            *(uint4*)&sB[bn * 40 + k] = make_uint4(h0, l0, h1, l1);
        }
        __syncthreads();

        // ---- compute: 2 k16-steps, 4x4 fragments, 3 MMAs each ----
#pragma unroll
        for (int ks = 0; ks < 2; ks++) {
            uint2 a[4][4], b[4][2];
#pragma unroll
            for (int mt = 0; mt < 4; mt++) {
                const int base2 = ((wm * 64 + mt * 16 + g) * 20 + ks * 8 + t) * 2;
                a[mt][0] = *(const uint2*)&sA[base2];
                a[mt][1] = *(const uint2*)&sA[base2 + 320];   // +8 rows
                a[mt][2] = *(const uint2*)&sA[base2 + 8];     // +4 pairs
                a[mt][3] = *(const uint2*)&sA[base2 + 328];
            }
#pragma unroll
            for (int nt = 0; nt < 4; nt++) {
                const int base2 = ((wn * 32 + nt * 8 + g) * 20 + ks * 8 + t) * 2;
                b[nt][0] = *(const uint2*)&sB[base2];
                b[nt][1] = *(const uint2*)&sB[base2 + 8];
            }
#pragma unroll
            for (int mt = 0; mt < 4; mt++)
#pragma unroll
                for (int nt = 0; nt < 4; nt++) {
                    mma16816(acc[mt][nt], a[mt][0].x, a[mt][1].x, a[mt][2].x, a[mt][3].x,
                             b[nt][0].x, b[nt][1].x);
                    mma16816(acc[mt][nt], a[mt][0].x, a[mt][1].x, a[mt][2].x, a[mt][3].x,
                             b[nt][0].y, b[nt][1].y);
                    mma16816(acc[mt][nt], a[mt][0].y, a[mt][1].y, a[mt][2].y, a[mt][3].y,
                             b[nt][0].x, b[nt][1].x);
                }
        }
    }

    // ---- epilogue (unchanged) ----
#pragma unroll
    for (int mt = 0; mt < 4; mt++) {
        const int mrow0 = m0 + wm * 64 + mt * 16 + g;
#pragma unroll
        for (int nt = 0; nt < 4; nt++) {
            const int c = n0 + wn * 32 + nt * 8 + 2 * t;
            const float b0 = bias[c], b1 = bias[c + 1];
            const float v00 = acc[mt][nt][0] + b0;
            const float v01 = acc[mt][nt][1] + b1;
            const float v10 = acc[mt][nt][2] + b0;
            const float v11 = acc[mt][nt][3] + b1;
            if (SCATTER) {
                const int which = c >> 10;
                const int cc = c & (DM - 1);
                const int h  = cc >> 6;
                const int d  = cc & (DH - 1);
                float* dst = (which == 0) ? g_Q : (which == 1) ? g_K : g_V;
#pragma unroll
                for (int rr = 0; rr < 2; rr++) {
                    const int m   = mrow0 + rr * 8;
                    const int bb  = m >> 11;
                    const int tok = m & (T_SEQ - 1);
                    const size_t idx = ((size_t)(bb * NH + h) * T_SEQ + tok) * DH + d;
                    *(float2*)&dst[idx] = rr ? make_float2(v10, v11)
                                             : make_float2(v00, v01);
                }
            } else {
                *(float2*)&out[(size_t)mrow0 * DM + c]       = make_float2(v00, v01);
                *(float2*)&out[(size_t)(mrow0 + 8) * DM + c] = make_float2(v10, v11);
            }
        }
    }
}

// ---------------------------------------------------------------------------
// Attention: R15 structure (hoisted LDGs, 4 CTAs/SM) + NEW hi/lo-interleaved
// smem (word = row*72 + 2*pair + {0,1}, stride 36 pairs): fragment loads are
// LDS.64 (conflict-free, (4g+t) mod 16 distinct per phase), Q/K staging is
// STS.128, V staging STS.64. Smem bytes identical (55296). exp2f softmax
// with log2(e) folded into Q's pre-scale (kills the FMUL inside __expf).
// ---------------------------------------------------------------------------
__global__ __launch_bounds__(128, 4)
void attn_mma_kernel()
{
    extern __shared__ unsigned smu[];
    unsigned* sQ = smu;                 // 64 rows x 72 words
    unsigned* sK = smu + 64 * 72;
    unsigned* sV = smu + 2 * 64 * 72;   // rows = d, pairs = keypair

    const int tid  = threadIdx.x;
    const int lane = tid & 31;
    const int w    = tid >> 5;      // warp 0..3, rows 16w..16w+15
    const int g    = lane >> 2;     // 0..7
    const int t    = lane & 3;      // 0..3
    const int qt   = (int)(gridDim.x - 1) - (int)blockIdx.x;  // longest first
    const int bh   = blockIdx.y;
    const int q0   = qt * 64;

    const float* Qg = g_Q + (size_t)bh * T_SEQ * DH;
    const float* Kg = g_K + (size_t)bh * T_SEQ * DH;
    const float* Vg = g_V + (size_t)bh * T_SEQ * DH;

    // staging maps (constant across iterations)
    const int krow = tid >> 4;                 // row base (step 8)
    const int kdq  = (tid & 15) << 2;          // d offset (0,4,..,60)
    const int vr   = tid & 31;                 // V key pair
    const int vd0  = (tid >> 5) << 2;          // V d base (stride 16 over i)

    // Q pre-scale: (1/sqrt(64)) * log2(e)  -> softmax in base-2 domain.
    const float QSCALE = 0.125f * 1.4426950408889634f;

    // ---- stage Q once ----
#pragma unroll
    for (int i = 0; i < 8; i++) {
        const int row = krow + i * 8;
        float4 v = *(const float4*)&Qg[(q0 + row) * DH + kdq];
        unsigned h0, l0, h1, l1;
        split2(v.x * QSCALE, v.y * QSCALE, h0, l0);
        split2(v.z * QSCALE, v.w * QSCALE, h1, l1);
        *(uint4*)&sQ[row * 72 + kdq] = make_uint4(h0, l0, h1, l1);
    }

    float oacc[8][4];
#pragma unroll
    for (int nf = 0; nf < 8; nf++)
#pragma unroll
        for (int i = 0; i < 4; i++) oacc[nf][i] = 0.f;
    float mrun0 = -INFINITY, mrun1 = -INFINITY;
    float lrun0 = 0.f, lrun1 = 0.f;

    for (int kt = 0; kt <= qt; kt++) {
        const int k0 = kt * 64;

        // ---- issue ALL K/V loads BEFORE the barrier ----
        float4 kv[8];
#pragma unroll
        for (int i = 0; i < 8; i++)
            kv[i] = *(const float4*)&Kg[(k0 + krow + i * 8) * DH + kdq];
        float4 va[4], vb[4];
#pragma unroll
        for (int i = 0; i < 4; i++) {
            const float* p0 = &Vg[(size_t)(k0 + 2 * vr) * DH + vd0 + i * 16];
            va[i] = *(const float4*)p0;
            vb[i] = *(const float4*)(p0 + DH);
        }
        __syncthreads();   // prior compute done reading smem (skew hides LDGs)

        // ---- split + vector STS ----
#pragma unroll
        for (int i = 0; i < 8; i++) {
            const int row = krow + i * 8;
            unsigned h0, l0, h1, l1;
            split2(kv[i].x, kv[i].y, h0, l0);
            split2(kv[i].z, kv[i].w, h1, l1);
            *(uint4*)&sK[row * 72 + kdq] = make_uint4(h0, l0, h1, l1);
        }
#pragma unroll
        for (int i = 0; i < 4; i++) {
            const int d = vd0 + i * 16;
            unsigned h, l;
            split2(va[i].x, vb[i].x, h, l); *(uint2*)&sV[(d + 0) * 72 + 2 * vr] = make_uint2(h, l);
            split2(va[i].y, vb[i].y, h, l); *(uint2*)&sV[(d + 1) * 72 + 2 * vr] = make_uint2(h, l);
            split2(va[i].z, vb[i].z, h, l); *(uint2*)&sV[(d + 2) * 72 + 2 * vr] = make_uint2(h, l);
            split2(va[i].w, vb[i].w, h, l); *(uint2*)&sV[(d + 3) * 72 + 2 * vr] = make_uint2(h, l);
        }
        __syncthreads();

        // ---- S = Q K^T : 8 n-frags x 4 k-steps x 3 MMAs (LDS.64 frags) ----
        float sacc[8][4];
#pragma unroll
        for (int nf = 0; nf < 8; nf++)
#pragma unroll
            for (int i = 0; i < 4; i++) sacc[nf][i] = 0.f;

#pragma unroll
        for (int ks = 0; ks < 4; ks++) {
            const int qp2 = ((16 * w + g) * 36 + ks * 8 + t) * 2;
            const uint2 q0f = *(const uint2*)&sQ[qp2];         // (qh0,ql0)
            const uint2 q2f = *(const uint2*)&sQ[qp2 + 8];     // (qh2,ql2)
            const uint2 q1f = *(const uint2*)&sQ[qp2 + 576];   // row+8
            const uint2 q3f = *(const uint2*)&sQ[qp2 + 584];
#pragma unroll
            for (int nf = 0; nf < 8; nf++) {
                const int kp2 = ((8 * nf + g) * 36 + ks * 8 + t) * 2;
                const uint2 k0f = *(const uint2*)&sK[kp2];
                const uint2 k1f = *(const uint2*)&sK[kp2 + 8];
                mma16816(sacc[nf], q0f.x, q1f.x, q2f.x, q3f.x, k0f.x, k1f.x);
                mma16816(sacc[nf], q0f.x, q1f.x, q2f.x, q3f.x, k0f.y, k1f.y);
                mma16816(sacc[nf], q0f.y, q1f.y, q2f.y, q3f.y, k0f.x, k1f.x);
            }
        }

        // ---- causal mask on the diagonal tile ----
        if (kt == qt) {
            const int r0 = 16 * w + g, r1 = r0 + 8;
#pragma unroll
            for (int nf = 0; nf < 8; nf++) {
                const int c = 8 * nf + 2 * t;
                if (c     > r0) sacc[nf][0] = -INFINITY;
                if (c + 1 > r0) sacc[nf][1] = -INFINITY;
                if (c     > r1) sacc[nf][2] = -INFINITY;
                if (c + 1 > r1) sacc[nf][3] = -INFINITY;
            }
        }

        // ---- online softmax (base-2 domain; rows g, g+8) ----
        float rm0 = -INFINITY, rm1 = -INFINITY;
#pragma unroll
        for (int nf = 0; nf < 8; nf++) {
            rm0 = fmaxf(rm0, fmaxf(sacc[nf][0], sacc[nf][1]));
            rm1 = fmaxf(rm1, fmaxf(sacc[nf][2], sacc[nf][3]));
        }
        rm0 = fmaxf(rm0, __shfl_xor_sync(0xffffffffu, rm0, 1));
        rm0 = fmaxf(rm0, __shfl_xor_sync(0xffffffffu, rm0, 2));
        rm1 = fmaxf(rm1, __shfl_xor_sync(0xffffffffu, rm1, 1));
        rm1 = fmaxf(rm1, __shfl_xor_sync(0xffffffffu, rm1, 2));

        const float mn0 = fmaxf(mrun0, rm0);
        const float mn1 = fmaxf(mrun1, rm1);
        const float c0  = exp2f(mrun0 - mn0);
        const float c1  = exp2f(mrun1 - mn1);

        float rs0 = 0.f, rs1 = 0.f;
#pragma unroll
        for (int nf = 0; nf < 8; nf++) {
            sacc[nf][0] = exp2f(sacc[nf][0] - mn0); rs0 += sacc[nf][0];
            sacc[nf][1] = exp2f(sacc[nf][1] - mn0); rs0 += sacc[nf][1];
            sacc[nf][2] = exp2f(sacc[nf][2] - mn1); rs1 += sacc[nf][2];
            sacc[nf][3] = exp2f(sacc[nf][3] - mn1); rs1 += sacc[nf][3];
        }
        rs0 += __shfl_xor_sync(0xffffffffu, rs0, 1);
        rs0 += __shfl_xor_sync(0xffffffffu, rs0, 2);
        rs1 += __shfl_xor_sync(0xffffffffu, rs1, 1);
        rs1 += __shfl_xor_sync(0xffffffffu, rs1, 2);

        lrun0 = lrun0 * c0 + rs0;
        lrun1 = lrun1 * c1 + rs1;
        mrun0 = mn0;
        mrun1 = mn1;
#pragma unroll
        for (int nf = 0; nf < 8; nf++) {
            oacc[nf][0] *= c0; oacc[nf][1] *= c0;
            oacc[nf][2] *= c1; oacc[nf][3] *= c1;
        }

        // ---- O += P V : S's C-fragments ARE P's A-fragments ----
#pragma unroll
        for (int ks = 0; ks < 4; ks++) {
            unsigned ph0, pl0, ph1, pl1, ph2, pl2, ph3, pl3;
            split2(sacc[2 * ks][0],     sacc[2 * ks][1],     ph0, pl0);
            split2(sacc[2 * ks][2],     sacc[2 * ks][3],     ph1, pl1);
            split2(sacc[2 * ks + 1][0], sacc[2 * ks + 1][1], ph2, pl2);
            split2(sacc[2 * ks + 1][2], sacc[2 * ks + 1][3], ph3, pl3);
#pragma unroll
            for (int nf = 0; nf < 8; nf++) {
                const int vp2 = ((8 * nf + g) * 36 + ks * 8 + t) * 2;
                const uint2 v0f = *(const uint2*)&sV[vp2];
                const uint2 v1f = *(const uint2*)&sV[vp2 + 8];
                mma16816(oacc[nf], ph0, ph1, ph2, ph3, v0f.x, v1f.x);
                mma16816(oacc[nf], ph0, ph1, ph2, ph3, v0f.y, v1f.y);
                mma16816(oacc[nf], pl0, pl1, pl2, pl3, v0f.x, v1f.x);
            }
        }
    }

    // ---- normalize and write to g_attn in [B,T,C] (C = h*64 + d) ----
    const float inv0 = 1.f / lrun0;
    const float inv1 = 1.f / lrun1;
    const int b  = bh >> 4;
    const int h  = bh & 15;
    const int r0 = q0 + 16 * w + g;
    const int r1 = r0 + 8;
#pragma unroll
    for (int nf = 0; nf < 8; nf++) {
        const int c = h * DH + 8 * nf + 2 * t;
        *(float2*)&g_attn[(size_t)(b * T_SEQ + r0) * DM + c] =
            make_float2(oacc[nf][0] * inv0, oacc[nf][1] * inv0);
        *(float2*)&g_attn[(size_t)(b * T_SEQ + r1) * DM + c] =
            make_float2(oacc[nf][2] * inv1, oacc[nf][3] * inv1);
    }
}

// ---------------------------------------------------------------------------
extern "C" void kernel_launch(void* const* d_in, const int* in_sizes, int n_in,
                              void* d_out, int out_size)
{
    const float* x      = (const float*)d_in[0];
    const float* W_qkv  = (const float*)d_in[1];
    const float* b_qkv  = (const float*)d_in[2];
    const float* W_proj = (const float*)d_in[3];
    const float* b_proj = (const float*)d_in[4];
    float* out = (float*)d_out;

    (void)in_sizes; (void)n_in; (void)out_size;

    const int attn_smem = 3 * 64 * 72 * 4;   // 55296 B (unchanged)
    cudaFuncSetAttribute(attn_mma_kernel,
                         cudaFuncAttributeMaxDynamicSharedMemorySize, attn_smem);

    dim3 gA(N_QKV / 128, MROWS / 128);   // (24, 32)
    mma_gemm_kernel<N_QKV, true><<<gA, 256>>>(x, W_qkv, b_qkv, nullptr);

    dim3 gB(T_SEQ / 64, BATCH * NH);     // (32, 32)
    attn_mma_kernel<<<gB, 128, attn_smem>>>();

    dim3 gC(DM / 128, MROWS / 128);      // (8, 32)
    mma_gemm_kernel<DM, false><<<gC, 256>>>(nullptr, W_proj, b_proj, out);
}